// round 9
// baseline (speedup 1.0000x reference)
#include <cuda_runtime.h>

#define BB 512
#define TT 512
#define IN_DIM 256
#define NJ 32          // 4 gates * 8 qubits
#define DTOT 264
#define ROWS (BB*TT)

// scratch: input projection, layout [row][q*4+g]  (q = qubit, g = gate f,i,g,o)
__device__ float g_proj[(size_t)ROWS * NJ];

typedef unsigned long long ull;

__device__ __forceinline__ ull pack2(float lo, float hi) {
    ull r;
    asm("mov.b64 %0, {%1, %2};" : "=l"(r) : "r"(__float_as_uint(lo)), "r"(__float_as_uint(hi)));
    return r;
}
__device__ __forceinline__ ull fma2(ull a, ull b, ull c) {
    ull d;
    asm("fma.rn.f32x2 %0, %1, %2, %3;" : "=l"(d) : "l"(a), "l"(b), "l"(c));
    return d;
}

// ---------------- GEMM: proj[r][q*4+g] = sum_k x[r][k] * W_g[q][k] ----------------
// 256 threads, 2 rows/thread, explicit distance-2 prefetch of x through registers.
__global__ void __launch_bounds__(256) gemm_kernel(
    const float* __restrict__ x,
    const float* __restrict__ Wf, const float* __restrict__ Wi,
    const float* __restrict__ Wg, const float* __restrict__ Wo)
{
    __shared__ __align__(16) float ws[IN_DIM * NJ];     // [k][q*4+g], 32 KB
    const int tid = threadIdx.x;

    for (int e = tid; e < IN_DIM * NJ; e += 256) {
        int k = e >> 5, j = e & 31;
        int q = j >> 2, g = j & 3;
        const float* Wp = (g == 0) ? Wf : (g == 1) ? Wi : (g == 2) ? Wg : Wo;
        ws[e] = Wp[q * DTOT + k];
    }
    __syncthreads();

    const size_t row0 = (size_t)blockIdx.x * 512 + tid;   // second row: row0 + 256
    const float4* x0 = reinterpret_cast<const float4*>(x + row0 * IN_DIM);
    const float4* x1 = reinterpret_cast<const float4*>(x + (row0 + 256) * IN_DIM);

    ull acc0[16], acc1[16];
    #pragma unroll
    for (int p = 0; p < 16; p++) { acc0[p] = 0ull; acc1[p] = 0ull; }

    // distance-2 prefetch pipeline for x
    float4 a0 = x0[0], b0 = x1[0];
    float4 a1 = x0[1], b1 = x1[1];

    for (int k4 = 0; k4 < IN_DIM / 4; k4++) {
        float4 a = a0, b = b0;
        a0 = a1; b0 = b1;
        int kn = k4 + 2; kn = (kn > IN_DIM / 4 - 1) ? (IN_DIM / 4 - 1) : kn;
        a1 = x0[kn]; b1 = x1[kn];

        float xa[4] = {a.x, a.y, a.z, a.w};
        float xb[4] = {b.x, b.y, b.z, b.w};
        #pragma unroll
        for (int kk = 0; kk < 4; kk++) {
            const double2* wv = reinterpret_cast<const double2*>(ws + (k4 * 4 + kk) * NJ);
            ull pa = pack2(xa[kk], xa[kk]);
            ull pb = pack2(xb[kk], xb[kk]);
            #pragma unroll
            for (int p4 = 0; p4 < 8; p4++) {
                double2 wd = wv[p4];
                ull w0 = (ull)__double_as_longlong(wd.x);
                ull w1 = (ull)__double_as_longlong(wd.y);
                acc0[2*p4]   = fma2(pa, w0, acc0[2*p4]);
                acc0[2*p4+1] = fma2(pa, w1, acc0[2*p4+1]);
                acc1[2*p4]   = fma2(pb, w0, acc1[2*p4]);
                acc1[2*p4+1] = fma2(pb, w1, acc1[2*p4+1]);
            }
        }
    }

    double2* o0 = reinterpret_cast<double2*>(g_proj + row0 * NJ);
    double2* o1 = reinterpret_cast<double2*>(g_proj + (row0 + 256) * NJ);
    #pragma unroll
    for (int p4 = 0; p4 < 8; p4++) {
        double2 v0, v1;
        v0.x = __longlong_as_double((long long)acc0[2*p4]);
        v0.y = __longlong_as_double((long long)acc0[2*p4+1]);
        v1.x = __longlong_as_double((long long)acc1[2*p4]);
        v1.y = __longlong_as_double((long long)acc1[2*p4+1]);
        o0[p4] = v0;
        o1[p4] = v1;
    }
}

// ---------------- activations: pure FMA / one RCP, valid on proven input ranges ----
// sigmoid(x), |x|<=1: 0.5 + x*poly(x^2), odd Taylor deg 9, err < 2.2e-6
__device__ __forceinline__ float sigp(float x) {
    float u = x * x;
    float p = fmaf(u, 2.1356922e-5f, -2.1081349e-4f);
    p = fmaf(u, p, 2.0833334e-3f);
    p = fmaf(u, p, -2.0833334e-2f);
    p = fmaf(u, p, 0.25f);
    return fmaf(x, p, 0.5f);
}
// tanh(x), |x|<=2.1: Pade x*(945+105u+u^2)/(945+420u+15u^2), err <= 7e-5
__device__ __forceinline__ float tanhp(float x) {
    float u = x * x;
    float N = fmaf(u, u + 105.0f, 945.0f);
    float D = fmaf(u, fmaf(15.0f, u, 420.0f), 945.0f);
    return __fdividef(x * N, D);
}

// ---------------- recurrence: one warp per 8 batches, TWO interleaved streams -----
// lane = sub*8 + qubit; stream 0: batches base+0..3, stream 1: batches base+4..7
__global__ void __launch_bounds__(32) recur_kernel(
    const float* __restrict__ Wf, const float* __restrict__ bf,
    const float* __restrict__ Wi, const float* __restrict__ bi,
    const float* __restrict__ Wg, const float* __restrict__ bg,
    const float* __restrict__ Wo, const float* __restrict__ bo,
    const float* __restrict__ thetas, float* __restrict__ out)
{
    const unsigned FULL = 0xffffffffu;
    const int lane = threadIdx.x;
    const int q = lane & 7;

    const float* Wptr[4] = {Wf, Wi, Wg, Wo};
    const float* bptr[4] = {bf, bi, bg, bo};

    float wh[4][8];
    float bt[4];
    #pragma unroll
    for (int g = 0; g < 4; g++) {
        #pragma unroll
        for (int k = 0; k < 8; k++) wh[g][k] = Wptr[g][q * DTOT + IN_DIM + k];
        bt[g] = bptr[g][q] + thetas[g * 8 + q];
    }

    // loop-invariant lane predicates / source index
    const bool ge1 = (q >= 1), ge2 = (q >= 2), ge4 = (q >= 4);
    const bool q0  = (q == 0);
    const bool q7  = (q == 7);
    const int  src = q0 ? 7 : 0;

    // two independent streams
    int batch[2];
    batch[0] = blockIdx.x * 8 + (lane >> 3);
    batch[1] = batch[0] + 4;

    const float4* pr[2];
    float4 pb0[2], pb1[2], pb2[2];
    float hx[2], cx[2];
    float* outp[2];
    #pragma unroll
    for (int s = 0; s < 2; s++) {
        pr[s] = reinterpret_cast<const float4*>(g_proj + (size_t)batch[s] * TT * NJ) + q;
        pb0[s] = pr[s][0];
        pb1[s] = pr[s][8];
        pb2[s] = pr[s][16];
        hx[s] = 0.f; cx[s] = 0.f;
        outp[s] = out + (size_t)batch[s] * TT * 8 + q;
    }

    for (int t = 0; t < TT; t++) {
        int tn = t + 3; tn = (tn > TT - 1) ? (TT - 1) : tn;

        #pragma unroll
        for (int s = 0; s < 2; s++) {
            float4 pin = pb0[s];
            pb0[s] = pb1[s]; pb1[s] = pb2[s];
            pb2[s] = pr[s][(size_t)tn * 8];

            // broadcast hidden state
            float hxv[8];
            #pragma unroll
            for (int k = 0; k < 8; k++) hxv[k] = __shfl_sync(FULL, hx[s], k, 8);

            float ang[4];
            ang[0] = pin.x + bt[0]; ang[1] = pin.y + bt[1];
            ang[2] = pin.z + bt[2]; ang[3] = pin.w + bt[3];
            #pragma unroll
            for (int g = 0; g < 4; g++) {
                float s0 = fmaf(wh[g][0], hxv[0], fmaf(wh[g][2], hxv[2],
                           fmaf(wh[g][4], hxv[4], wh[g][6] * hxv[6])));
                float s1 = fmaf(wh[g][1], hxv[1], fmaf(wh[g][3], hxv[3],
                           fmaf(wh[g][5], hxv[5], wh[g][7] * hxv[7])));
                ang[g] += s0 + s1;
            }

            // analytic circuit: masked up-scan, p_q = prod_{1..q} c (lane0 seeded 1)
            float c[4], p[4];
            #pragma unroll
            for (int g = 0; g < 4; g++) {
                c[g] = __cosf(ang[g]);
                p[g] = q0 ? 1.0f : c[g];
            }
            #pragma unroll
            for (int g = 0; g < 4; g++) {
                float v = __shfl_up_sync(FULL, p[g], 1, 8);
                p[g] *= ge1 ? v : 1.0f;
            }
            #pragma unroll
            for (int g = 0; g < 4; g++) {
                float v = __shfl_up_sync(FULL, p[g], 2, 8);
                p[g] *= ge2 ? v : 1.0f;
            }
            #pragma unroll
            for (int g = 0; g < 4; g++) {
                float v = __shfl_up_sync(FULL, p[g], 4, 8);
                p[g] *= ge4 ? v : 1.0f;
            }
            // merged fixup: lane0 reads p_7 (= m_0); lanes 1..7 read c_0
            float m[4];
            #pragma unroll
            for (int g = 0; g < 4; g++) {
                float z = q7 ? p[g] : c[g];
                float w = __shfl_sync(FULL, z, src, 8);
                m[g] = q0 ? w : w * p[g];
            }

            float f_ = sigp(m[0]);
            float i_ = sigp(m[1]);
            float gg = tanhp(m[2]);
            float o_ = sigp(m[3]);

            cx[s] = fmaf(f_, cx[s], i_ * gg);       // |cx| <= 2.07
            hx[s] = o_ * tanhp(cx[s]);

            outp[s][(size_t)t * 8] = hx[s];
        }
    }

    #pragma unroll
    for (int s = 0; s < 2; s++) {
        out[(size_t)BB * TT * 8 + (size_t)batch[s] * 8 + q] = hx[s];                   // final hx
        out[(size_t)BB * TT * 8 + (size_t)BB * 8 + (size_t)batch[s] * 8 + q] = cx[s];  // final cx
    }
}

extern "C" void kernel_launch(void* const* d_in, const int* in_sizes, int n_in,
                              void* d_out, int out_size) {
    (void)in_sizes; (void)n_in; (void)out_size;
    const float* x  = (const float*)d_in[0];
    const float* Wf = (const float*)d_in[1]; const float* bf = (const float*)d_in[2];
    const float* Wi = (const float*)d_in[3]; const float* bi = (const float*)d_in[4];
    const float* Wg = (const float*)d_in[5]; const float* bg = (const float*)d_in[6];
    const float* Wo = (const float*)d_in[7]; const float* bo = (const float*)d_in[8];
    const float* th = (const float*)d_in[9];
    float* out = (float*)d_out;

    gemm_kernel<<<ROWS / 512, 256>>>(x, Wf, Wi, Wg, Wo);
    recur_kernel<<<BB / 8, 32>>>(Wf, bf, Wi, bi, Wg, bg, Wo, bo, th, out);
}

// round 11
// speedup vs baseline: 1.1837x; 1.1837x over previous
#include <cuda_runtime.h>

#define BB 512
#define TT 512
#define IN_DIM 256
#define NJ 32          // 4 gates * 8 qubits
#define DTOT 264
#define ROWS (BB*TT)

// scratch: input projection, layout [row][q*4+g]  (q = qubit, g = gate f,i,g,o)
__device__ float g_proj[(size_t)ROWS * NJ];

typedef unsigned long long ull;

__device__ __forceinline__ ull pack2(float lo, float hi) {
    ull r;
    asm("mov.b64 %0, {%1, %2};" : "=l"(r) : "r"(__float_as_uint(lo)), "r"(__float_as_uint(hi)));
    return r;
}
__device__ __forceinline__ ull fma2(ull a, ull b, ull c) {
    ull d;
    asm("fma.rn.f32x2 %0, %1, %2, %3;" : "=l"(d) : "l"(a), "l"(b), "l"(c));
    return d;
}

// ---------------- GEMM: proj[r][q*4+g] = sum_k x[r][k] * W_g[q][k] ----------------
// 256 threads, 2 rows/thread, explicit distance-2 prefetch of x through registers.
__global__ void __launch_bounds__(256) gemm_kernel(
    const float* __restrict__ x,
    const float* __restrict__ Wf, const float* __restrict__ Wi,
    const float* __restrict__ Wg, const float* __restrict__ Wo)
{
    __shared__ __align__(16) float ws[IN_DIM * NJ];     // [k][q*4+g], 32 KB
    const int tid = threadIdx.x;

    for (int e = tid; e < IN_DIM * NJ; e += 256) {
        int k = e >> 5, j = e & 31;
        int q = j >> 2, g = j & 3;
        const float* Wp = (g == 0) ? Wf : (g == 1) ? Wi : (g == 2) ? Wg : Wo;
        ws[e] = Wp[q * DTOT + k];
    }
    __syncthreads();

    const size_t row0 = (size_t)blockIdx.x * 512 + tid;   // second row: row0 + 256
    const float4* x0 = reinterpret_cast<const float4*>(x + row0 * IN_DIM);
    const float4* x1 = reinterpret_cast<const float4*>(x + (row0 + 256) * IN_DIM);

    ull acc0[16], acc1[16];
    #pragma unroll
    for (int p = 0; p < 16; p++) { acc0[p] = 0ull; acc1[p] = 0ull; }

    // distance-2 prefetch pipeline for x
    float4 a0 = x0[0], b0 = x1[0];
    float4 a1 = x0[1], b1 = x1[1];

    for (int k4 = 0; k4 < IN_DIM / 4; k4++) {
        float4 a = a0, b = b0;
        a0 = a1; b0 = b1;
        int kn = k4 + 2; kn = (kn > IN_DIM / 4 - 1) ? (IN_DIM / 4 - 1) : kn;
        a1 = x0[kn]; b1 = x1[kn];

        float xa[4] = {a.x, a.y, a.z, a.w};
        float xb[4] = {b.x, b.y, b.z, b.w};
        #pragma unroll
        for (int kk = 0; kk < 4; kk++) {
            const double2* wv = reinterpret_cast<const double2*>(ws + (k4 * 4 + kk) * NJ);
            ull pa = pack2(xa[kk], xa[kk]);
            ull pb = pack2(xb[kk], xb[kk]);
            #pragma unroll
            for (int p4 = 0; p4 < 8; p4++) {
                double2 wd = wv[p4];
                ull w0 = (ull)__double_as_longlong(wd.x);
                ull w1 = (ull)__double_as_longlong(wd.y);
                acc0[2*p4]   = fma2(pa, w0, acc0[2*p4]);
                acc0[2*p4+1] = fma2(pa, w1, acc0[2*p4+1]);
                acc1[2*p4]   = fma2(pb, w0, acc1[2*p4]);
                acc1[2*p4+1] = fma2(pb, w1, acc1[2*p4+1]);
            }
        }
    }

    double2* o0 = reinterpret_cast<double2*>(g_proj + row0 * NJ);
    double2* o1 = reinterpret_cast<double2*>(g_proj + (row0 + 256) * NJ);
    #pragma unroll
    for (int p4 = 0; p4 < 8; p4++) {
        double2 v0, v1;
        v0.x = __longlong_as_double((long long)acc0[2*p4]);
        v0.y = __longlong_as_double((long long)acc0[2*p4+1]);
        v1.x = __longlong_as_double((long long)acc1[2*p4]);
        v1.y = __longlong_as_double((long long)acc1[2*p4+1]);
        o0[p4] = v0;
        o1[p4] = v1;
    }
}

// ---------------- activations: pure FMA / one RCP, valid on proven input ranges ----
// sigmoid(x), |x|<=1: 0.5 + x*poly(x^2), odd Taylor deg 9, err < 2.2e-6
__device__ __forceinline__ float sigp(float x) {
    float u = x * x;
    float p = fmaf(u, 2.1356922e-5f, -2.1081349e-4f);
    p = fmaf(u, p, 2.0833334e-3f);
    p = fmaf(u, p, -2.0833334e-2f);
    p = fmaf(u, p, 0.25f);
    return fmaf(x, p, 0.5f);
}
// tanh(x), |x|<=2.1: Pade x*(945+105u+u^2)/(945+420u+15u^2), err <= 7e-5
__device__ __forceinline__ float tanhp(float x) {
    float u = x * x;
    float N = fmaf(u, u + 105.0f, 945.0f);
    float D = fmaf(u, fmaf(15.0f, u, 420.0f), 945.0f);
    return __fdividef(x * N, D);
}

// ---------------- recurrence: one warp per 4 batches, SMEM exchange (no shuffles) --
// lane = sub*8 + qubit. hx and cosines exchanged through shared memory; every lane
// then computes its own circuit expectation with lane-local selects (no cross-lane
// dependency stages beyond the two STS/LDS round-trips).
#define CS_STRIDE 36   // floats per sub-batch in cs[] (144B: keeps subs on distinct banks)

__global__ void __launch_bounds__(32) recur_kernel(
    const float* __restrict__ Wf, const float* __restrict__ bf,
    const float* __restrict__ Wi, const float* __restrict__ bi,
    const float* __restrict__ Wg, const float* __restrict__ bg,
    const float* __restrict__ Wo, const float* __restrict__ bo,
    const float* __restrict__ thetas, float* __restrict__ out)
{
    __shared__ __align__(16) float hxs[32];                  // [sub][qubit]
    __shared__ __align__(16) float cs[4 * CS_STRIDE];        // [sub][qubit][gate] float4, padded

    const int lane = threadIdx.x;
    const int q   = lane & 7;
    const int sub = lane >> 3;
    const int wg  = blockIdx.x * 4 + sub;   // batch index

    const float* Wptr[4] = {Wf, Wi, Wg, Wo};
    const float* bptr[4] = {bf, bi, bg, bo};

    float wh[4][8];
    float bt[4];
    #pragma unroll
    for (int g = 0; g < 4; g++) {
        #pragma unroll
        for (int k = 0; k < 8; k++) wh[g][k] = Wptr[g][q * DTOT + IN_DIM + k];
        bt[g] = bptr[g][q] + thetas[g * 8 + q];
    }

    // lane-constant product masks: include c_k in my product iff (k<=q) or q==0 (k>=1)
    const bool q0 = (q == 0);
    bool inc[8];
    #pragma unroll
    for (int k = 1; k < 8; k++) inc[k] = (k <= q) || q0;

    const float4* pr = reinterpret_cast<const float4*>(g_proj + (size_t)wg * TT * NJ) + q;
    float4 pb0 = pr[0];
    float4 pb1 = pr[8];
    float4 pb2 = pr[16];

    hxs[lane] = 0.0f;
    __syncwarp();

    float cx = 0.f;
    float* outp = out + (size_t)wg * TT * 8 + q;

    float* myc  = cs + sub * CS_STRIDE + q * 4;
    const float4* grpc = reinterpret_cast<const float4*>(cs + sub * CS_STRIDE);
    const float4* grph = reinterpret_cast<const float4*>(hxs + sub * 8);

    for (int t = 0; t < TT; t++) {
        float4 pin = pb0;
        pb0 = pb1; pb1 = pb2;
        int tn = t + 3; tn = (tn > TT - 1) ? (TT - 1) : tn;
        pb2 = pr[(size_t)tn * 8];

        // read full hidden state of my sub-batch (broadcast LDS)
        float4 h0 = grph[0];
        float4 h1 = grph[1];
        float hv[8] = {h0.x, h0.y, h0.z, h0.w, h1.x, h1.y, h1.z, h1.w};

        float ang[4];
        ang[0] = pin.x + bt[0]; ang[1] = pin.y + bt[1];
        ang[2] = pin.z + bt[2]; ang[3] = pin.w + bt[3];
        #pragma unroll
        for (int g = 0; g < 4; g++) {
            float s0 = fmaf(wh[g][0], hv[0], fmaf(wh[g][2], hv[2],
                       fmaf(wh[g][4], hv[4], wh[g][6] * hv[6])));
            float s1 = fmaf(wh[g][1], hv[1], fmaf(wh[g][3], hv[3],
                       fmaf(wh[g][5], hv[5], wh[g][7] * hv[7])));
            ang[g] += s0 + s1;
        }

        // publish my 4 cosines
        float4 cw;
        cw.x = __cosf(ang[0]); cw.y = __cosf(ang[1]);
        cw.z = __cosf(ang[2]); cw.w = __cosf(ang[3]);
        *reinterpret_cast<float4*>(myc) = cw;
        __syncwarp();

        // read all 8 qubits' cosines for my sub-batch (broadcast LDS.128 x8)
        float4 cq[8];
        #pragma unroll
        for (int k = 0; k < 8; k++) cq[k] = grpc[k];

        // my expectation per gate: m = (q==0 ? 1 : c_0) * prod_{k>=1, inc[k]} c_k
        float m[4];
        #pragma unroll
        for (int g = 0; g < 4; g++) {
            float ck[8];
            ck[0] = (g == 0) ? cq[0].x : (g == 1) ? cq[0].y : (g == 2) ? cq[0].z : cq[0].w;
            #pragma unroll
            for (int k = 1; k < 8; k++) {
                float v = (g == 0) ? cq[k].x : (g == 1) ? cq[k].y : (g == 2) ? cq[k].z : cq[k].w;
                ck[k] = inc[k] ? v : 1.0f;
            }
            float head = q0 ? 1.0f : ck[0];
            float t01 = ck[1] * ck[2];
            float t23 = ck[3] * ck[4];
            float t45 = ck[5] * ck[6];
            m[g] = (head * t01) * (t23 * (t45 * ck[7]));
        }

        // gates: |m|<=1 guaranteed
        float f_ = sigp(m[0]);
        float i_ = sigp(m[1]);
        float gg = tanhp(m[2]);
        float o_ = sigp(m[3]);

        cx = fmaf(f_, cx, i_ * gg);          // |cx| <= 2.07
        float hx = o_ * tanhp(cx);

        outp[(size_t)t * 8] = hx;
        hxs[lane] = hx;
        __syncwarp();
    }

    float hx_final = hxs[lane];
    out[(size_t)BB * TT * 8 + (size_t)wg * 8 + q] = hx_final;                  // final hx
    out[(size_t)BB * TT * 8 + (size_t)BB * 8 + (size_t)wg * 8 + q] = cx;       // final cx
}

extern "C" void kernel_launch(void* const* d_in, const int* in_sizes, int n_in,
                              void* d_out, int out_size) {
    (void)in_sizes; (void)n_in; (void)out_size;
    const float* x  = (const float*)d_in[0];
    const float* Wf = (const float*)d_in[1]; const float* bf = (const float*)d_in[2];
    const float* Wi = (const float*)d_in[3]; const float* bi = (const float*)d_in[4];
    const float* Wg = (const float*)d_in[5]; const float* bg = (const float*)d_in[6];
    const float* Wo = (const float*)d_in[7]; const float* bo = (const float*)d_in[8];
    const float* th = (const float*)d_in[9];
    float* out = (float*)d_out;

    gemm_kernel<<<ROWS / 512, 256>>>(x, Wf, Wi, Wg, Wo);
    recur_kernel<<<BB / 4, 32>>>(Wf, bf, Wi, bi, Wg, bg, Wo, bo, th, out);
}

// round 14
// speedup vs baseline: 1.5160x; 1.2808x over previous
#include <cuda_runtime.h>

#define BB 512
#define TT 512
#define IN_DIM 256
#define NJ 32          // 4 gates * 8 qubits
#define DTOT 264
#define ROWS (BB*TT)

// scratch: input projection, layout [row][q*4+g]  (q = qubit, g = gate f,i,g,o)
__device__ float g_proj[(size_t)ROWS * NJ];

typedef unsigned long long ull;

__device__ __forceinline__ ull pack2(float lo, float hi) {
    ull r;
    asm("mov.b64 %0, {%1, %2};" : "=l"(r) : "r"(__float_as_uint(lo)), "r"(__float_as_uint(hi)));
    return r;
}
__device__ __forceinline__ ull fma2(ull a, ull b, ull c) {
    ull d;
    asm("fma.rn.f32x2 %0, %1, %2, %3;" : "=l"(d) : "l"(a), "l"(b), "l"(c));
    return d;
}

// ---------------- GEMM: proj[r][q*4+g] = sum_k x[r][k] * W_g[q][k] ----------------
// 256 threads, 2 rows/thread, REAL distance-3 prefetch: 4-slot modular buffer,
// fully unrolled so the LDG destination register is untouched for 3 iterations.
__global__ void __launch_bounds__(256) gemm_kernel(
    const float* __restrict__ x,
    const float* __restrict__ Wf, const float* __restrict__ Wi,
    const float* __restrict__ Wg, const float* __restrict__ Wo)
{
    __shared__ __align__(16) float ws[IN_DIM * NJ];     // [k][q*4+g], 32 KB
    const int tid = threadIdx.x;

    for (int e = tid; e < IN_DIM * NJ; e += 256) {
        int k = e >> 5, j = e & 31;
        int q = j >> 2, g = j & 3;
        const float* Wp = (g == 0) ? Wf : (g == 1) ? Wi : (g == 2) ? Wg : Wo;
        ws[e] = Wp[q * DTOT + k];
    }
    __syncthreads();

    const size_t row0 = (size_t)blockIdx.x * 512 + tid;   // second row: row0 + 256
    const float4* x0 = reinterpret_cast<const float4*>(x + row0 * IN_DIM);
    const float4* x1 = reinterpret_cast<const float4*>(x + (row0 + 256) * IN_DIM);

    ull acc0[16], acc1[16];
    #pragma unroll
    for (int p = 0; p < 16; p++) { acc0[p] = 0ull; acc1[p] = 0ull; }

    // 4-slot prefetch buffers, slot = k4 & 3
    float4 abuf[4], bbuf[4];
    abuf[0] = x0[0]; bbuf[0] = x1[0];
    abuf[1] = x0[1]; bbuf[1] = x1[1];
    abuf[2] = x0[2]; bbuf[2] = x1[2];

    const int NK4 = IN_DIM / 4;   // 64
    for (int k40 = 0; k40 < NK4; k40 += 4) {
        #pragma unroll
        for (int u = 0; u < 4; u++) {
            const int k4 = k40 + u;
            float4 a = abuf[u];
            float4 b = bbuf[u];
            int kn = k4 + 3; kn = (kn > NK4 - 1) ? (NK4 - 1) : kn;
            abuf[(u + 3) & 3] = x0[kn];
            bbuf[(u + 3) & 3] = x1[kn];

            float xa[4] = {a.x, a.y, a.z, a.w};
            float xb[4] = {b.x, b.y, b.z, b.w};
            #pragma unroll
            for (int kk = 0; kk < 4; kk++) {
                const double2* wv = reinterpret_cast<const double2*>(ws + (k4 * 4 + kk) * NJ);
                ull pa = pack2(xa[kk], xa[kk]);
                ull pb = pack2(xb[kk], xb[kk]);
                #pragma unroll
                for (int p4 = 0; p4 < 8; p4++) {
                    double2 wd = wv[p4];
                    ull w0 = (ull)__double_as_longlong(wd.x);
                    ull w1 = (ull)__double_as_longlong(wd.y);
                    acc0[2*p4]   = fma2(pa, w0, acc0[2*p4]);
                    acc0[2*p4+1] = fma2(pa, w1, acc0[2*p4+1]);
                    acc1[2*p4]   = fma2(pb, w0, acc1[2*p4]);
                    acc1[2*p4+1] = fma2(pb, w1, acc1[2*p4+1]);
                }
            }
        }
    }

    double2* o0 = reinterpret_cast<double2*>(g_proj + row0 * NJ);
    double2* o1 = reinterpret_cast<double2*>(g_proj + (row0 + 256) * NJ);
    #pragma unroll
    for (int p4 = 0; p4 < 8; p4++) {
        double2 v0, v1;
        v0.x = __longlong_as_double((long long)acc0[2*p4]);
        v0.y = __longlong_as_double((long long)acc0[2*p4+1]);
        v1.x = __longlong_as_double((long long)acc1[2*p4]);
        v1.y = __longlong_as_double((long long)acc1[2*p4+1]);
        o0[p4] = v0;
        o1[p4] = v1;
    }
}

// ---------------- activations: pure FMA / one RCP, valid on proven input ranges ----
// sigmoid(x), |x|<=1: 0.5 + x*poly(x^2), odd Taylor deg 9, err < 2.2e-6
__device__ __forceinline__ float sigp(float x) {
    float u = x * x;
    float p = fmaf(u, 2.1356922e-5f, -2.1081349e-4f);
    p = fmaf(u, p, 2.0833334e-3f);
    p = fmaf(u, p, -2.0833334e-2f);
    p = fmaf(u, p, 0.25f);
    return fmaf(x, p, 0.5f);
}
// tanh(x), |x|<=2.1: Pade x*(945+105u+u^2)/(945+420u+15u^2), err <= 7e-5
__device__ __forceinline__ float tanhp(float x) {
    float u = x * x;
    float N = fmaf(u, u + 105.0f, 945.0f);
    float D = fmaf(u, fmaf(15.0f, u, 420.0f), 945.0f);
    return __fdividef(x * N, D);
}

// ---------------- recurrence: one warp per 4 batches, SMEM exchange ----------------
// lane = sub*8 + qubit. hx and cosines exchanged through shared memory; every lane
// computes its own circuit expectation lane-locally. g_proj reads use a REAL
// distance-3 prefetch (4-slot modular buffer, loop unrolled x4).
#define CS_STRIDE 36   // floats per sub-batch in cs[] (144B: keeps subs on distinct banks)

__global__ void __launch_bounds__(32) recur_kernel(
    const float* __restrict__ Wf, const float* __restrict__ bf,
    const float* __restrict__ Wi, const float* __restrict__ bi,
    const float* __restrict__ Wg, const float* __restrict__ bg,
    const float* __restrict__ Wo, const float* __restrict__ bo,
    const float* __restrict__ thetas, float* __restrict__ out)
{
    __shared__ __align__(16) float hxs[32];                  // [sub][qubit]
    __shared__ __align__(16) float cs[4 * CS_STRIDE];        // [sub][qubit][gate] float4, padded

    const int lane = threadIdx.x;
    const int q   = lane & 7;
    const int sub = lane >> 3;
    const int wg  = blockIdx.x * 4 + sub;   // batch index

    const float* Wptr[4] = {Wf, Wi, Wg, Wo};
    const float* bptr[4] = {bf, bi, bg, bo};

    float wh[4][8];
    float bt[4];
    #pragma unroll
    for (int g = 0; g < 4; g++) {
        #pragma unroll
        for (int k = 0; k < 8; k++) wh[g][k] = Wptr[g][q * DTOT + IN_DIM + k];
        bt[g] = bptr[g][q] + thetas[g * 8 + q];
    }

    // lane-constant product masks: include c_k in my product iff (k<=q) or q==0 (k>=1)
    const bool q0 = (q == 0);
    bool inc[8];
    #pragma unroll
    for (int k = 1; k < 8; k++) inc[k] = (k <= q) || q0;

    const float4* pr = reinterpret_cast<const float4*>(g_proj + (size_t)wg * TT * NJ) + q;

    // 4-slot prefetch buffer, slot = t & 3
    float4 pbuf[4];
    pbuf[0] = pr[0];
    pbuf[1] = pr[8];
    pbuf[2] = pr[16];

    hxs[lane] = 0.0f;
    __syncwarp();

    float cx = 0.f;
    float* outp = out + (size_t)wg * TT * 8 + q;

    float* myc  = cs + sub * CS_STRIDE + q * 4;
    const float4* grpc = reinterpret_cast<const float4*>(cs + sub * CS_STRIDE);
    const float4* grph = reinterpret_cast<const float4*>(hxs + sub * 8);

    for (int t0 = 0; t0 < TT; t0 += 4) {
        #pragma unroll
        for (int u = 0; u < 4; u++) {
            const int t = t0 + u;
            float4 pin = pbuf[u];
            int tn = t + 3; tn = (tn > TT - 1) ? (TT - 1) : tn;
            pbuf[(u + 3) & 3] = pr[(size_t)tn * 8];

            // read full hidden state of my sub-batch (broadcast LDS)
            float4 h0 = grph[0];
            float4 h1 = grph[1];
            float hv[8] = {h0.x, h0.y, h0.z, h0.w, h1.x, h1.y, h1.z, h1.w};

            float ang[4];
            ang[0] = pin.x + bt[0]; ang[1] = pin.y + bt[1];
            ang[2] = pin.z + bt[2]; ang[3] = pin.w + bt[3];
            #pragma unroll
            for (int g = 0; g < 4; g++) {
                float s0 = fmaf(wh[g][0], hv[0], fmaf(wh[g][2], hv[2],
                           fmaf(wh[g][4], hv[4], wh[g][6] * hv[6])));
                float s1 = fmaf(wh[g][1], hv[1], fmaf(wh[g][3], hv[3],
                           fmaf(wh[g][5], hv[5], wh[g][7] * hv[7])));
                ang[g] += s0 + s1;
            }

            // publish my 4 cosines
            float4 cw;
            cw.x = __cosf(ang[0]); cw.y = __cosf(ang[1]);
            cw.z = __cosf(ang[2]); cw.w = __cosf(ang[3]);
            *reinterpret_cast<float4*>(myc) = cw;
            __syncwarp();

            // read all 8 qubits' cosines for my sub-batch (broadcast LDS.128 x8)
            float4 cq[8];
            #pragma unroll
            for (int k = 0; k < 8; k++) cq[k] = grpc[k];

            // my expectation per gate: m = (q==0 ? 1 : c_0) * prod_{k>=1, inc[k]} c_k
            float m[4];
            #pragma unroll
            for (int g = 0; g < 4; g++) {
                float ck[8];
                ck[0] = (g == 0) ? cq[0].x : (g == 1) ? cq[0].y : (g == 2) ? cq[0].z : cq[0].w;
                #pragma unroll
                for (int k = 1; k < 8; k++) {
                    float v = (g == 0) ? cq[k].x : (g == 1) ? cq[k].y : (g == 2) ? cq[k].z : cq[k].w;
                    ck[k] = inc[k] ? v : 1.0f;
                }
                float head = q0 ? 1.0f : ck[0];
                float t01 = ck[1] * ck[2];
                float t23 = ck[3] * ck[4];
                float t45 = ck[5] * ck[6];
                m[g] = (head * t01) * (t23 * (t45 * ck[7]));
            }

            // gates: |m|<=1 guaranteed
            float f_ = sigp(m[0]);
            float i_ = sigp(m[1]);
            float gg = tanhp(m[2]);
            float o_ = sigp(m[3]);

            cx = fmaf(f_, cx, i_ * gg);          // |cx| <= 2.07
            float hx = o_ * tanhp(cx);

            outp[(size_t)t * 8] = hx;
            hxs[lane] = hx;
            __syncwarp();
        }
    }

    float hx_final = hxs[lane];
    out[(size_t)BB * TT * 8 + (size_t)wg * 8 + q] = hx_final;                  // final hx
    out[(size_t)BB * TT * 8 + (size_t)BB * 8 + (size_t)wg * 8 + q] = cx;       // final cx
}

extern "C" void kernel_launch(void* const* d_in, const int* in_sizes, int n_in,
                              void* d_out, int out_size) {
    (void)in_sizes; (void)n_in; (void)out_size;
    const float* x  = (const float*)d_in[0];
    const float* Wf = (const float*)d_in[1]; const float* bf = (const float*)d_in[2];
    const float* Wi = (const float*)d_in[3]; const float* bi = (const float*)d_in[4];
    const float* Wg = (const float*)d_in[5]; const float* bg = (const float*)d_in[6];
    const float* Wo = (const float*)d_in[7]; const float* bo = (const float*)d_in[8];
    const float* th = (const float*)d_in[9];
    float* out = (float*)d_out;

    gemm_kernel<<<ROWS / 512, 256>>>(x, Wf, Wi, Wg, Wo);
    recur_kernel<<<BB / 4, 32>>>(Wf, bf, Wi, bi, Wg, bg, Wo, bo, th, out);
}